// round 11
// baseline (speedup 1.0000x reference)
#include <cuda_runtime.h>
#include <cuda_bf16.h>
#include <math.h>
#include <stdint.h>

// Problem constants
#define NPIX      131072          // 4 * (16384 main + 16384 aux)
#define SELBLK    512
#define NBLK      (NPIX / SELBLK) // 256
#define C_CLS     20
#define MEMM      512
#define AROWS     (C_CLS * MEMM)  // 10240
#define DIM       256
#define IGNORE_I  255
#define AUX_I     254

// Persistent GEMM tiling
#define TM        256             // band rows (A resident)
#define TN        128             // col tile
#define NCT       80              // col tiles per band
#define NTILE     3200            // 40 bands * 80
#define GRID_P    148
#define GTH       512             // GEMM threads (16 warps, 4x4)
#define PADA_B    528             // A smem row stride bytes
#define PADB_B    144             // B smem row stride bytes (64 bf16 + pad)
#define A_BYTES   (256 * PADA_B)  // 135168
#define B_STG     (128 * PADB_B)  // 18432
#define SMO_B     A_BYTES
#define SMO_CV    (A_BYTES + 4 * B_STG)   // 208896
#define SMEM_T    (SMO_CV + 1024)         // 209920

// -------- persistent scratch ------------------------------------------------
__device__ int   g_blockCounts[NBLK * C_CLS];
__device__ int   g_blockOffsets[NBLK * C_CLS];
__device__ int   g_counts[C_CLS];
__device__ int   g_selIdx[AROWS];
__device__ __nv_bfloat16 g_selb[AROWS * DIM];
__device__ __nv_bfloat16 g_contrasb[AROWS * DIM];
__device__ float g_cvalid[AROWS];
__device__ int   g_cvSum[C_CLS];
__device__ float g_rowExp[AROWS];
__device__ float g_rowPos[AROWS];

// ----------------------------- ptx helpers ----------------------------------
__device__ __forceinline__ uint32_t smem_u32(const void* p) {
    uint32_t a;
    asm("{ .reg .u64 t; cvta.to.shared.u64 t, %1; cvt.u32.u64 %0, t; }"
        : "=r"(a) : "l"(p));
    return a;
}

#define CP_ASYNC16(dst, src) \
    asm volatile("cp.async.cg.shared.global [%0], [%1], 16;" :: "r"(dst), "l"(src))
#define CP_ASYNC4(dst, src) \
    asm volatile("cp.async.ca.shared.global [%0], [%1], 4;" :: "r"(dst), "l"(src))
#define CP_COMMIT() asm volatile("cp.async.commit_group;" ::: "memory")
#define CP_WAIT(n)  asm volatile("cp.async.wait_group %0;" :: "n"(n) : "memory")

#define LDSM_X4(r0, r1, r2, r3, addr)                                          \
    asm volatile("ldmatrix.sync.aligned.m8n8.x4.shared.b16 {%0,%1,%2,%3}, [%4];" \
        : "=r"(r0), "=r"(r1), "=r"(r2), "=r"(r3) : "r"(addr))

__device__ __forceinline__ void mma_bf16(float c[4], const uint32_t a[4],
                                         uint32_t b0, uint32_t b1) {
    asm volatile(
        "mma.sync.aligned.m16n8k16.row.col.f32.bf16.bf16.f32 "
        "{%0,%1,%2,%3}, {%4,%5,%6,%7}, {%8,%9}, {%0,%1,%2,%3};"
        : "+f"(c[0]), "+f"(c[1]), "+f"(c[2]), "+f"(c[3])
        : "r"(a[0]), "r"(a[1]), "r"(a[2]), "r"(a[3]), "r"(b0), "r"(b1));
}

__device__ __forceinline__ int pix_label(int n, const int* __restrict__ mg,
                                         const int* __restrict__ ag) {
    int b = n >> 15;
    int j = n & 32767;
    int lab;
    if (j < 16384) {
        int h = j >> 7, w = j & 127;
        lab = mg[(b << 18) + (h << 11) + (w << 2)];
    } else {
        int jj = j - 16384;
        int h = jj >> 7, w = jj & 127;
        lab = ag[(b << 18) + (h << 11) + (w << 2)];
    }
    return lab;
}

// ------------------------------ prep kernels (r7 proven) ---------------------
__global__ void k_initcount(const int* __restrict__ mg, const int* __restrict__ ag) {
    __shared__ int hist[C_CLS];
    int tid = threadIdx.x;
    int t = blockIdx.x * SELBLK + tid;
    if (t < AROWS) {
        g_selIdx[t] = -1;
        g_rowExp[t] = 0.f;
        g_rowPos[t] = 0.f;
    }
    if (t < C_CLS) g_cvSum[t] = 0;
    if (tid < C_CLS) hist[tid] = 0;
    __syncthreads();
    int lab = pix_label(t, mg, ag);
    if (lab != IGNORE_I) {
        if (lab == AUX_I) lab = C_CLS - 1;
        atomicAdd(&hist[lab], 1);
    }
    __syncthreads();
    if (tid < C_CLS)
        g_blockCounts[blockIdx.x * C_CLS + tid] = hist[tid];
}

__global__ void k_scan() {
    int w = threadIdx.x >> 5, lane = threadIdx.x & 31;
    if (w >= C_CLS) return;
    int carry = 0;
    #pragma unroll
    for (int seg = 0; seg < 8; seg++) {
        int b = seg * 32 + lane;
        int v = g_blockCounts[b * C_CLS + w];
        int incl = v;
        #pragma unroll
        for (int o = 1; o < 32; o <<= 1) {
            int tt = __shfl_up_sync(0xffffffffu, incl, o);
            if (lane >= o) incl += tt;
        }
        g_blockOffsets[b * C_CLS + w] = carry + incl - v;
        carry += __shfl_sync(0xffffffffu, incl, 31);
    }
    if (lane == 0) g_counts[w] = carry;
}

__global__ void k_select(const int* __restrict__ mg, const int* __restrict__ ag) {
    __shared__ int warpHist[16][C_CLS];
    int tid = threadIdx.x, wid = tid >> 5, lane = tid & 31;
    for (int i = tid; i < 16 * C_CLS; i += SELBLK) ((int*)warpHist)[i] = 0;
    __syncthreads();
    int n = blockIdx.x * SELBLK + tid;
    int lab = pix_label(n, mg, ag);
    bool valid = (lab != IGNORE_I);
    if (lab == AUX_I) lab = C_CLS - 1;
    int key = valid ? lab : IGNORE_I;
    unsigned mask = __match_any_sync(0xffffffffu, key);
    int rank = __popc(mask & ((1u << lane) - 1u));
    if (valid && rank == 0) warpHist[wid][lab] = __popc(mask);
    __syncthreads();
    if (valid) {
        int base = g_blockOffsets[blockIdx.x * C_CLS + lab];
        for (int w2 = 0; w2 < wid; w2++) base += warpHist[w2][lab];
        int slot = base + rank;
        if (slot < MEMM) g_selIdx[lab * MEMM + slot] = n;
    }
}

__global__ void k_gatherbank(const float* __restrict__ mp, const float* __restrict__ ap,
                             const float* __restrict__ bank) {
    int wslot = blockIdx.x * 8 + (threadIdx.x >> 5);
    int lane = threadIdx.x & 31;
    if (wslot >= AROWS) return;
    int n = g_selIdx[wslot];
    int c = wslot >> 9;
    __nv_bfloat16* sdst = g_selb + (size_t)wslot * DIM;
    __nv_bfloat16* cdst = g_contrasb + (size_t)wslot * DIM;
    const float* br = bank + (size_t)wslot * DIM;

    float u[8];
    float ss = 0.f;
    if (n >= 0) {
        int b = n >> 15, j = n & 32767;
        const float* src;
        if (j < 16384) {
            int h = j >> 7, w = j & 127;
            src = mp + ((size_t)b << 22) + (h << 7) + w;
        } else {
            int jj = j - 16384;
            int h = jj >> 7, w = jj & 127;
            src = ap + ((size_t)b << 22) + (h << 7) + w;
        }
        float v[8];
        float vs = 0.f;
        #pragma unroll
        for (int k = 0; k < 8; k++) {
            v[k] = src[(size_t)(lane + k * 32) << 14];
            vs += v[k] * v[k];
        }
        #pragma unroll
        for (int off = 16; off; off >>= 1) vs += __shfl_xor_sync(0xffffffffu, vs, off);
        float inv = 1.f / fmaxf(sqrtf(vs), 1e-12f);
        #pragma unroll
        for (int k = 0; k < 8; k++) {
            float s = v[k] * inv;
            sdst[lane + k * 32] = __float2bfloat16(s);
            float uu = 0.999f * br[lane + k * 32] + 0.001f * s;
            u[k] = uu;
            ss += uu * uu;
        }
        #pragma unroll
        for (int off = 16; off; off >>= 1) ss += __shfl_xor_sync(0xffffffffu, ss, off);
        float inv2 = 1.f / fmaxf(sqrtf(ss), 1e-12f);
        #pragma unroll
        for (int k = 0; k < 8; k++)
            cdst[lane + k * 32] = __float2bfloat16(u[k] * inv2);
    } else {
        #pragma unroll
        for (int k = 0; k < 8; k++) {
            sdst[lane + k * 32] = __float2bfloat16(0.f);
            float uu = br[lane + k * 32];
            u[k] = uu;
            ss += uu * uu;
            cdst[lane + k * 32] = __float2bfloat16(uu);
        }
        #pragma unroll
        for (int off = 16; off; off >>= 1) ss += __shfl_xor_sync(0xffffffffu, ss, off);
    }
    if (lane == 0) {
        float cv = (ss > 0.f) ? 1.f : 0.f;
        g_cvalid[wslot] = cv;
        if (cv > 0.f) atomicAdd(&g_cvSum[c], 1);
    }
}

// -------------- persistent bf16 GEMM: 16 warps (4x4), warp tile 64x32 --------
__global__ void __launch_bounds__(GTH, 1) k_gemm_p() {
    extern __shared__ char sm[];
    const uint32_t aBase = smem_u32(sm);
    const uint32_t bBase = aBase + SMO_B;
    const uint32_t cvBase = aBase + SMO_CV;
    float* cvs = (float*)(sm + SMO_CV);

    const int tid = threadIdx.x, lane = tid & 31, wid = tid >> 5;
    const int tig = lane & 3, grp = lane >> 2;
    const int wr = wid >> 2, wc = wid & 3;

    const int aRow = wr * 64 + (lane & 15);
    const int aK   = (lane >> 4) * 8;
    const int bg   = lane >> 3;
    const int bRow = wc * 32 + ((bg >> 1) << 3) + (lane & 7);
    const int bK   = (bg & 1) * 8;

    int t0 = (int)(((long long)blockIdx.x * NTILE) / GRID_P);
    int t1 = (int)(((long long)(blockIdx.x + 1) * NTILE) / GRID_P);

    float c[4][4][4];
    float eAcc[4][2], pAcc[4][2];
    #pragma unroll
    for (int mi = 0; mi < 4; mi++) {
        #pragma unroll
        for (int ni = 0; ni < 4; ni++)
            #pragma unroll
            for (int q = 0; q < 4; q++) c[mi][ni][q] = 0.f;
        eAcc[mi][0] = eAcc[mi][1] = 0.f;
        pAcc[mi][0] = pAcc[mi][1] = 0.f;
    }

    int t = t0;
    while (t < t1) {
        const int band = t / NCT;
        const int ct0 = t % NCT;
        int bandEnd = (band + 1) * NCT;
        if (bandEnd > t1) bandEnd = t1;
        const int nt = bandEnd - t;
        const int total = nt * 4;
        const __nv_bfloat16* Ag = g_selb + (size_t)band * TM * DIM;

        // A band: 8192 16B chunks, 512 threads -> 16 iters
        #pragma unroll
        for (int i = 0; i < 16; i++) {
            int ch = tid + i * GTH;
            int r = ch >> 5, seg = ch & 31;
            CP_ASYNC16(aBase + r * PADA_B + seg * 16,
                       (const char*)(Ag + (size_t)r * DIM + seg * 8));
        }
        CP_COMMIT();

        auto issue_stage = [&](int g) {
            const int ti = g >> 2, kq = g & 3;
            const int ct = ct0 + ti;
            const __nv_bfloat16* Bg =
                g_contrasb + ((size_t)ct * TN) * DIM + kq * 64;
            const uint32_t bb = bBase + (g & 3) * B_STG;
            #pragma unroll
            for (int i = 0; i < 2; i++) {
                int ch = tid + i * GTH;
                int r = ch >> 3, seg = ch & 7;
                CP_ASYNC16(bb + r * PADB_B + seg * 16,
                           (const char*)(Bg + (size_t)r * DIM + seg * 8));
            }
            if (kq == 0 && tid < TN) {
                CP_ASYNC4(cvBase + (ti & 1) * 512 + tid * 4,
                          (const char*)(g_cvalid + ct * TN + tid));
            }
        };

        issue_stage(0); CP_COMMIT();
        issue_stage(1); CP_COMMIT();
        issue_stage(2); CP_COMMIT();

        for (int s = 0; s < total; s++) {
            if (s < total - 2)      { CP_WAIT(2); }
            else if (s == total - 2){ CP_WAIT(1); }
            else                    { CP_WAIT(0); }
            __syncthreads();

            if (s + 3 < total) {
                issue_stage(s + 3);
                CP_COMMIT();
            }

            const uint32_t bb = bBase + (s & 3) * B_STG;
            const int kb = (s & 3) * 64;
            #pragma unroll
            for (int ks = 0; ks < 4; ks++) {
                const int kcA = kb + ks * 16;
                const int kcB = ks * 16;
                uint32_t af[4][4];
                #pragma unroll
                for (int mi = 0; mi < 4; mi++) {
                    uint32_t addr = aBase + (aRow + mi * 16) * PADA_B + (kcA + aK) * 2;
                    LDSM_X4(af[mi][0], af[mi][1], af[mi][2], af[mi][3], addr);
                }
                uint32_t bf[4][2];
                #pragma unroll
                for (int p = 0; p < 2; p++) {
                    uint32_t addr = bb + (bRow + p * 16) * PADB_B + (kcB + bK) * 2;
                    uint32_t r0, r1, r2, r3;
                    LDSM_X4(r0, r1, r2, r3, addr);
                    bf[2 * p][0] = r0; bf[2 * p][1] = r1;
                    bf[2 * p + 1][0] = r2; bf[2 * p + 1][1] = r3;
                }
                #pragma unroll
                for (int mi = 0; mi < 4; mi++)
                    #pragma unroll
                    for (int ni = 0; ni < 4; ni++)
                        mma_bf16(c[mi][ni], af[mi], bf[ni][0], bf[ni][1]);
            }

            if ((s & 3) == 3) {
                const int ti = s >> 2;
                const int ct = ct0 + ti;
                const float posf = ((band >> 1) == (ct >> 2)) ? 1.f : 0.f;
                const float* cv = cvs + (ti & 1) * 128;
                float cvr[4][2];
                #pragma unroll
                for (int ni = 0; ni < 4; ni++) {
                    cvr[ni][0] = cv[wc * 32 + ni * 8 + 2 * tig];
                    cvr[ni][1] = cv[wc * 32 + ni * 8 + 2 * tig + 1];
                }
                #pragma unroll
                for (int mi = 0; mi < 4; mi++)
                    #pragma unroll
                    for (int h = 0; h < 2; h++) {
                        float e = 0.f, p = 0.f;
                        #pragma unroll
                        for (int ni = 0; ni < 4; ni++)
                            #pragma unroll
                            for (int j = 0; j < 2; j++) {
                                float sc = c[mi][ni][h * 2 + j] * 10.0f;
                                e += cvr[ni][j] * __expf(sc);
                                p += cvr[ni][j] * sc;
                                c[mi][ni][h * 2 + j] = 0.f;
                            }
                        eAcc[mi][h] += e;
                        pAcc[mi][h] += posf * p;
                    }
            }
        }

        #pragma unroll
        for (int mi = 0; mi < 4; mi++)
            #pragma unroll
            for (int h = 0; h < 2; h++) {
                float e = eAcc[mi][h], p = pAcc[mi][h];
                e += __shfl_xor_sync(0xffffffffu, e, 1);
                e += __shfl_xor_sync(0xffffffffu, e, 2);
                p += __shfl_xor_sync(0xffffffffu, p, 1);
                p += __shfl_xor_sync(0xffffffffu, p, 2);
                if (tig == 0) {
                    int r = band * TM + wr * 64 + mi * 16 + h * 8 + grp;
                    atomicAdd(&g_rowExp[r], e);
                    atomicAdd(&g_rowPos[r], p);
                }
                eAcc[mi][h] = 0.f;
                pAcc[mi][h] = 0.f;
            }
        __syncthreads();
        t = bandEnd;
    }
}

// ------------------------------- loss ----------------------------------------
__global__ void k_loss(float* __restrict__ out) {
    __shared__ double sred[256];
    __shared__ int cred[256];
    int tid = threadIdx.x;
    double local = 0.0;
    int cnt = 0;
    for (int s = tid; s < AROWS; s += 256) {
        int c = s >> 9, m = s & 511;
        int pc = g_cvSum[c];
        if (m < g_counts[c] && pc > 0) {
            float lse = logf(g_rowExp[s]);
            float mlpp = (g_rowPos[s] - (float)pc * lse) / (float)pc;
            local += (double)mlpp;
            cnt++;
        }
    }
    sred[tid] = local;
    cred[tid] = cnt;
    __syncthreads();
    for (int off = 128; off; off >>= 1) {
        if (tid < off) {
            sred[tid] += sred[tid + off];
            cred[tid] += cred[tid + off];
        }
        __syncthreads();
    }
    if (tid == 0) {
        int n = cred[0] > 0 ? cred[0] : 1;
        out[0] = (float)(-sred[0] / (double)n);
    }
}

// ------------------------------- launcher ------------------------------------
extern "C" void kernel_launch(void* const* d_in, const int* in_sizes, int n_in,
                              void* d_out, int out_size) {
    const float* mp   = (const float*)d_in[0];
    const int*   mg   = (const int*)d_in[1];
    const float* ap   = (const float*)d_in[2];
    const int*   ag   = (const int*)d_in[3];
    const float* bank = (const float*)d_in[4];
    float* out = (float*)d_out;

    cudaFuncSetAttribute(k_gemm_p, cudaFuncAttributeMaxDynamicSharedMemorySize,
                         SMEM_T);

    k_initcount<<<NBLK, SELBLK>>>(mg, ag);
    k_scan<<<1, 640>>>();
    k_select<<<NBLK, SELBLK>>>(mg, ag);
    k_gatherbank<<<AROWS / 8, 256>>>(mp, ap, bank);
    k_gemm_p<<<GRID_P, GTH, SMEM_T>>>();
    k_loss<<<1, 256>>>(out);
}

// round 12
// speedup vs baseline: 1.1157x; 1.1157x over previous
#include <cuda_runtime.h>
#include <cuda_bf16.h>
#include <math.h>
#include <stdint.h>

// Problem constants
#define NPIX      131072          // 4 * (16384 main + 16384 aux)
#define SELBLK    512
#define NBLK      (NPIX / SELBLK) // 256
#define C_CLS     20
#define MEMM      512
#define AROWS     (C_CLS * MEMM)  // 10240
#define DIM       256
#define IGNORE_I  255
#define AUX_I     254

// Persistent GEMM tiling (round-7 proven config, verbatim)
#define TM        256             // band rows (A resident)
#define TN        128             // col tile
#define NCT       80              // col tiles per band
#define NTILE     3200            // 40 bands * 80
#define GRID_P    148
#define PADA_B    528             // A smem row stride bytes
#define PADB_B    144             // B smem row stride bytes (64 bf16 + pad)
#define A_BYTES   (256 * PADA_B)  // 135168
#define B_STG     (128 * PADB_B)  // 18432
#define SMO_B     A_BYTES
#define SMO_CV    (A_BYTES + 4 * B_STG)   // 208896
#define SMEM_T    (SMO_CV + 1024)         // 209920

// -------- persistent scratch ------------------------------------------------
__device__ int   g_blockCounts[NBLK * C_CLS];
__device__ int   g_counts[C_CLS];
__device__ int   g_selIdx[AROWS];
__device__ __nv_bfloat16 g_selb[AROWS * DIM];
__device__ __nv_bfloat16 g_contrasb[AROWS * DIM];
__device__ float g_cvalid[AROWS];
__device__ int   g_cvSum[C_CLS];
__device__ float g_rowExp[AROWS];
__device__ float g_rowPos[AROWS];

// ----------------------------- ptx helpers ----------------------------------
__device__ __forceinline__ uint32_t smem_u32(const void* p) {
    uint32_t a;
    asm("{ .reg .u64 t; cvta.to.shared.u64 t, %1; cvt.u32.u64 %0, t; }"
        : "=r"(a) : "l"(p));
    return a;
}

#define CP_ASYNC16(dst, src) \
    asm volatile("cp.async.cg.shared.global [%0], [%1], 16;" :: "r"(dst), "l"(src))
#define CP_ASYNC4(dst, src) \
    asm volatile("cp.async.ca.shared.global [%0], [%1], 4;" :: "r"(dst), "l"(src))
#define CP_COMMIT() asm volatile("cp.async.commit_group;" ::: "memory")
#define CP_WAIT(n)  asm volatile("cp.async.wait_group %0;" :: "n"(n) : "memory")

#define LDSM_X4(r0, r1, r2, r3, addr)                                          \
    asm volatile("ldmatrix.sync.aligned.m8n8.x4.shared.b16 {%0,%1,%2,%3}, [%4];" \
        : "=r"(r0), "=r"(r1), "=r"(r2), "=r"(r3) : "r"(addr))

__device__ __forceinline__ void mma_bf16(float c[4], const uint32_t a[4],
                                         uint32_t b0, uint32_t b1) {
    asm volatile(
        "mma.sync.aligned.m16n8k16.row.col.f32.bf16.bf16.f32 "
        "{%0,%1,%2,%3}, {%4,%5,%6,%7}, {%8,%9}, {%0,%1,%2,%3};"
        : "+f"(c[0]), "+f"(c[1]), "+f"(c[2]), "+f"(c[3])
        : "r"(a[0]), "r"(a[1]), "r"(a[2]), "r"(a[3]), "r"(b0), "r"(b1));
}

__device__ __forceinline__ int pix_label(int n, const int* __restrict__ mg,
                                         const int* __restrict__ ag) {
    int b = n >> 15;
    int j = n & 32767;
    int lab;
    if (j < 16384) {
        int h = j >> 7, w = j & 127;
        lab = mg[(b << 18) + (h << 11) + (w << 2)];
    } else {
        int jj = j - 16384;
        int h = jj >> 7, w = jj & 127;
        lab = ag[(b << 18) + (h << 11) + (w << 2)];
    }
    return lab;
}

// ------------------------------ prep kernels --------------------------------
__global__ void k_initcount(const int* __restrict__ mg, const int* __restrict__ ag) {
    __shared__ int hist[C_CLS];
    int tid = threadIdx.x;
    int t = blockIdx.x * SELBLK + tid;
    if (t < AROWS) {
        g_selIdx[t] = -1;
        g_rowExp[t] = 0.f;
        g_rowPos[t] = 0.f;
    }
    if (t < C_CLS) g_cvSum[t] = 0;
    if (tid < C_CLS) hist[tid] = 0;
    __syncthreads();
    int lab = pix_label(t, mg, ag);
    if (lab != IGNORE_I) {
        if (lab == AUX_I) lab = C_CLS - 1;
        atomicAdd(&hist[lab], 1);
    }
    __syncthreads();
    if (tid < C_CLS)
        g_blockCounts[blockIdx.x * C_CLS + tid] = hist[tid];
}

// fused scan + stable select: each CTA computes its own per-class base offset
__global__ void k_select(const int* __restrict__ mg, const int* __restrict__ ag) {
    __shared__ int warpHist[16][C_CLS];
    __shared__ int blockBase[C_CLS];
    int tid = threadIdx.x, wid = tid >> 5, lane = tid & 31;

    // per-class base = sum of blockCounts of preceding blocks (warp per class)
    for (int c = wid; c < C_CLS; c += 16) {
        int sum = 0;
        for (int b = lane; b < blockIdx.x; b += 32)
            sum += g_blockCounts[b * C_CLS + c];
        #pragma unroll
        for (int off = 16; off; off >>= 1)
            sum += __shfl_xor_sync(0xffffffffu, sum, off);
        if (lane == 0) {
            blockBase[c] = sum;
            if (blockIdx.x == NBLK - 1)
                g_counts[c] = sum + g_blockCounts[(NBLK - 1) * C_CLS + c];
        }
    }
    for (int i = tid; i < 16 * C_CLS; i += SELBLK) ((int*)warpHist)[i] = 0;
    __syncthreads();

    int n = blockIdx.x * SELBLK + tid;
    int lab = pix_label(n, mg, ag);
    bool valid = (lab != IGNORE_I);
    if (lab == AUX_I) lab = C_CLS - 1;
    int key = valid ? lab : IGNORE_I;
    unsigned mask = __match_any_sync(0xffffffffu, key);
    int rank = __popc(mask & ((1u << lane) - 1u));
    if (valid && rank == 0) warpHist[wid][lab] = __popc(mask);
    __syncthreads();
    if (valid) {
        int base = blockBase[lab];
        for (int w2 = 0; w2 < wid; w2++) base += warpHist[w2][lab];
        int slot = base + rank;
        if (slot < MEMM) g_selIdx[lab * MEMM + slot] = n;
    }
}

__global__ void k_gatherbank(const float* __restrict__ mp, const float* __restrict__ ap,
                             const float* __restrict__ bank) {
    int wslot = blockIdx.x * 8 + (threadIdx.x >> 5);
    int lane = threadIdx.x & 31;
    if (wslot >= AROWS) return;
    int n = g_selIdx[wslot];
    int c = wslot >> 9;
    __nv_bfloat16* sdst = g_selb + (size_t)wslot * DIM;
    __nv_bfloat16* cdst = g_contrasb + (size_t)wslot * DIM;
    const float* br = bank + (size_t)wslot * DIM;

    float u[8];
    float ss = 0.f;
    if (n >= 0) {
        int b = n >> 15, j = n & 32767;
        const float* src;
        if (j < 16384) {
            int h = j >> 7, w = j & 127;
            src = mp + ((size_t)b << 22) + (h << 7) + w;
        } else {
            int jj = j - 16384;
            int h = jj >> 7, w = jj & 127;
            src = ap + ((size_t)b << 22) + (h << 7) + w;
        }
        float v[8];
        float vs = 0.f;
        #pragma unroll
        for (int k = 0; k < 8; k++) {
            v[k] = src[(size_t)(lane + k * 32) << 14];
            vs += v[k] * v[k];
        }
        #pragma unroll
        for (int off = 16; off; off >>= 1) vs += __shfl_xor_sync(0xffffffffu, vs, off);
        float inv = 1.f / fmaxf(sqrtf(vs), 1e-12f);
        #pragma unroll
        for (int k = 0; k < 8; k++) {
            float s = v[k] * inv;
            sdst[lane + k * 32] = __float2bfloat16(s);
            float uu = 0.999f * br[lane + k * 32] + 0.001f * s;
            u[k] = uu;
            ss += uu * uu;
        }
        #pragma unroll
        for (int off = 16; off; off >>= 1) ss += __shfl_xor_sync(0xffffffffu, ss, off);
        float inv2 = 1.f / fmaxf(sqrtf(ss), 1e-12f);
        #pragma unroll
        for (int k = 0; k < 8; k++)
            cdst[lane + k * 32] = __float2bfloat16(u[k] * inv2);
    } else {
        #pragma unroll
        for (int k = 0; k < 8; k++) {
            sdst[lane + k * 32] = __float2bfloat16(0.f);
            float uu = br[lane + k * 32];
            u[k] = uu;
            ss += uu * uu;
            cdst[lane + k * 32] = __float2bfloat16(uu);
        }
        #pragma unroll
        for (int off = 16; off; off >>= 1) ss += __shfl_xor_sync(0xffffffffu, ss, off);
    }
    if (lane == 0) {
        float cv = (ss > 0.f) ? 1.f : 0.f;
        g_cvalid[wslot] = cv;
        if (cv > 0.f) atomicAdd(&g_cvSum[c], 1);
    }
}

// -------------- persistent bf16 GEMM (round-7 verbatim) ----------------------
// 148 CTAs, 256 threads (8 warps 4x2, warp tile 64x64, frags 4x8 m16n8k16).
__global__ void __launch_bounds__(256, 1) k_gemm_p() {
    extern __shared__ char sm[];
    const uint32_t aBase = smem_u32(sm);
    const uint32_t bBase = aBase + SMO_B;
    const uint32_t cvBase = aBase + SMO_CV;
    float* cvs = (float*)(sm + SMO_CV);

    const int tid = threadIdx.x, lane = tid & 31, wid = tid >> 5;
    const int tig = lane & 3, grp = lane >> 2;
    const int wr = wid >> 1, wc = wid & 1;

    const int aRow = wr * 64 + (lane & 15);
    const int aK   = (lane >> 4) * 8;
    const int bg   = lane >> 3;
    const int bRow = wc * 64 + ((bg >> 1) << 3) + (lane & 7);
    const int bK   = (bg & 1) * 8;

    int t0 = (int)(((long long)blockIdx.x * NTILE) / GRID_P);
    int t1 = (int)(((long long)(blockIdx.x + 1) * NTILE) / GRID_P);

    float c[4][8][4];
    float eAcc[4][2], pAcc[4][2];
    #pragma unroll
    for (int mi = 0; mi < 4; mi++) {
        #pragma unroll
        for (int ni = 0; ni < 8; ni++)
            #pragma unroll
            for (int q = 0; q < 4; q++) c[mi][ni][q] = 0.f;
        eAcc[mi][0] = eAcc[mi][1] = 0.f;
        pAcc[mi][0] = pAcc[mi][1] = 0.f;
    }

    int t = t0;
    while (t < t1) {
        const int band = t / NCT;
        const int ct0 = t % NCT;
        int bandEnd = (band + 1) * NCT;
        if (bandEnd > t1) bandEnd = t1;
        const int nt = bandEnd - t;
        const int total = nt * 4;
        const __nv_bfloat16* Ag = g_selb + (size_t)band * TM * DIM;

        #pragma unroll
        for (int i = 0; i < 32; i++) {
            int ch = tid + i * 256;
            int r = ch >> 5, seg = ch & 31;
            CP_ASYNC16(aBase + r * PADA_B + seg * 16,
                       (const char*)(Ag + (size_t)r * DIM + seg * 8));
        }
        CP_COMMIT();

        auto issue_stage = [&](int g) {
            const int ti = g >> 2, kq = g & 3;
            const int ct = ct0 + ti;
            const __nv_bfloat16* Bg =
                g_contrasb + ((size_t)ct * TN) * DIM + kq * 64;
            const uint32_t bb = bBase + (g & 3) * B_STG;
            #pragma unroll
            for (int i = 0; i < 4; i++) {
                int ch = tid + i * 256;
                int r = ch >> 3, seg = ch & 7;
                CP_ASYNC16(bb + r * PADB_B + seg * 16,
                           (const char*)(Bg + (size_t)r * DIM + seg * 8));
            }
            if (kq == 0 && tid < TN) {
                CP_ASYNC4(cvBase + (ti & 1) * 512 + tid * 4,
                          (const char*)(g_cvalid + ct * TN + tid));
            }
        };

        issue_stage(0); CP_COMMIT();
        issue_stage(1); CP_COMMIT();
        issue_stage(2); CP_COMMIT();

        for (int s = 0; s < total; s++) {
            if (s < total - 2)      { CP_WAIT(2); }
            else if (s == total - 2){ CP_WAIT(1); }
            else                    { CP_WAIT(0); }
            __syncthreads();

            const uint32_t bb = bBase + (s & 3) * B_STG;
            const int kb = (s & 3) * 64;
            #pragma unroll
            for (int ks = 0; ks < 4; ks++) {
                const int kcA = kb + ks * 16;
                const int kcB = ks * 16;
                uint32_t af[4][4];
                #pragma unroll
                for (int mi = 0; mi < 4; mi++) {
                    uint32_t addr = aBase + (aRow + mi * 16) * PADA_B + (kcA + aK) * 2;
                    LDSM_X4(af[mi][0], af[mi][1], af[mi][2], af[mi][3], addr);
                }
                uint32_t bf[8][2];
                #pragma unroll
                for (int p = 0; p < 4; p++) {
                    uint32_t addr = bb + (bRow + p * 16) * PADB_B + (kcB + bK) * 2;
                    uint32_t r0, r1, r2, r3;
                    LDSM_X4(r0, r1, r2, r3, addr);
                    bf[2 * p][0] = r0; bf[2 * p][1] = r1;
                    bf[2 * p + 1][0] = r2; bf[2 * p + 1][1] = r3;
                }
                #pragma unroll
                for (int mi = 0; mi < 4; mi++)
                    #pragma unroll
                    for (int ni = 0; ni < 8; ni++)
                        mma_bf16(c[mi][ni], af[mi], bf[ni][0], bf[ni][1]);
            }

            if ((s & 3) == 3) {
                const int ti = s >> 2;
                const int ct = ct0 + ti;
                const float posf = ((band >> 1) == (ct >> 2)) ? 1.f : 0.f;
                const float* cv = cvs + (ti & 1) * 128;
                float cvr[8][2];
                #pragma unroll
                for (int ni = 0; ni < 8; ni++) {
                    cvr[ni][0] = cv[wc * 64 + ni * 8 + 2 * tig];
                    cvr[ni][1] = cv[wc * 64 + ni * 8 + 2 * tig + 1];
                }
                #pragma unroll
                for (int mi = 0; mi < 4; mi++)
                    #pragma unroll
                    for (int h = 0; h < 2; h++) {
                        float e = 0.f, p = 0.f;
                        #pragma unroll
                        for (int ni = 0; ni < 8; ni++)
                            #pragma unroll
                            for (int j = 0; j < 2; j++) {
                                float sc = c[mi][ni][h * 2 + j] * 10.0f;
                                e += cvr[ni][j] * __expf(sc);
                                p += cvr[ni][j] * sc;
                                c[mi][ni][h * 2 + j] = 0.f;
                            }
                        eAcc[mi][h] += e;
                        pAcc[mi][h] += posf * p;
                    }
            }

            if (s + 3 < total) {
                issue_stage(s + 3);
                CP_COMMIT();
            }
        }

        #pragma unroll
        for (int mi = 0; mi < 4; mi++)
            #pragma unroll
            for (int h = 0; h < 2; h++) {
                float e = eAcc[mi][h], p = pAcc[mi][h];
                e += __shfl_xor_sync(0xffffffffu, e, 1);
                e += __shfl_xor_sync(0xffffffffu, e, 2);
                p += __shfl_xor_sync(0xffffffffu, p, 1);
                p += __shfl_xor_sync(0xffffffffu, p, 2);
                if (tig == 0) {
                    int r = band * TM + wr * 64 + mi * 16 + h * 8 + grp;
                    atomicAdd(&g_rowExp[r], e);
                    atomicAdd(&g_rowPos[r], p);
                }
                eAcc[mi][h] = 0.f;
                pAcc[mi][h] = 0.f;
            }
        __syncthreads();
        t = bandEnd;
    }
}

// ------------------------------- loss ----------------------------------------
__global__ void k_loss(float* __restrict__ out) {
    __shared__ double sred[256];
    __shared__ int cred[256];
    int tid = threadIdx.x;
    double local = 0.0;
    int cnt = 0;
    for (int s = tid; s < AROWS; s += 256) {
        int c = s >> 9, m = s & 511;
        int pc = g_cvSum[c];
        if (m < g_counts[c] && pc > 0) {
            float lse = logf(g_rowExp[s]);
            float mlpp = (g_rowPos[s] - (float)pc * lse) / (float)pc;
            local += (double)mlpp;
            cnt++;
        }
    }
    sred[tid] = local;
    cred[tid] = cnt;
    __syncthreads();
    for (int off = 128; off; off >>= 1) {
        if (tid < off) {
            sred[tid] += sred[tid + off];
            cred[tid] += cred[tid + off];
        }
        __syncthreads();
    }
    if (tid == 0) {
        int n = cred[0] > 0 ? cred[0] : 1;
        out[0] = (float)(-sred[0] / (double)n);
    }
}

// ------------------------------- launcher ------------------------------------
extern "C" void kernel_launch(void* const* d_in, const int* in_sizes, int n_in,
                              void* d_out, int out_size) {
    const float* mp   = (const float*)d_in[0];
    const int*   mg   = (const int*)d_in[1];
    const float* ap   = (const float*)d_in[2];
    const int*   ag   = (const int*)d_in[3];
    const float* bank = (const float*)d_in[4];
    float* out = (float*)d_out;

    cudaFuncSetAttribute(k_gemm_p, cudaFuncAttributeMaxDynamicSharedMemorySize,
                         SMEM_T);

    k_initcount<<<NBLK, SELBLK>>>(mg, ag);        // launch 1
    k_select<<<NBLK, SELBLK>>>(mg, ag);           // launch 2 (scan fused)
    k_gatherbank<<<AROWS / 8, 256>>>(mp, ap, bank); // launch 3
    k_gemm_p<<<GRID_P, 256, SMEM_T>>>();          // launch 4 -> ncu capture
    k_loss<<<1, 256>>>(out);                      // launch 5
}

// round 13
// speedup vs baseline: 1.1286x; 1.0116x over previous
#include <cuda_runtime.h>
#include <cuda_bf16.h>
#include <math.h>
#include <stdint.h>

// Problem constants
#define NPIX      131072          // 4 * (16384 main + 16384 aux)
#define SELBLK    512
#define NBLK      (NPIX / SELBLK) // 256
#define C_CLS     20
#define MEMM      512
#define AROWS     (C_CLS * MEMM)  // 10240
#define DIM       256
#define IGNORE_I  255
#define AUX_I     254

// Persistent GEMM tiling (round-7 proven config, verbatim)
#define TM        256             // band rows (A resident)
#define TN        128             // col tile
#define NCT       80              // col tiles per band
#define NTILE     3200            // 40 bands * 80
#define GRID_P    148
#define PADA_B    528             // A smem row stride bytes
#define PADB_B    144             // B smem row stride bytes (64 bf16 + pad)
#define A_BYTES   (256 * PADA_B)  // 135168
#define B_STG     (128 * PADB_B)  // 18432
#define SMO_B     A_BYTES
#define SMO_CV    (A_BYTES + 4 * B_STG)   // 208896
#define SMEM_T    (SMO_CV + 1024)         // 209920

// -------- persistent scratch ------------------------------------------------
__device__ int   g_blockCounts[NBLK * C_CLS];
__device__ int   g_counts[C_CLS];
__device__ int   g_selIdx[AROWS];
__device__ unsigned char g_lab[NPIX];
__device__ __nv_bfloat16 g_selb[AROWS * DIM];
__device__ __nv_bfloat16 g_contrasb[AROWS * DIM];
__device__ float g_cvalid[AROWS];
__device__ int   g_cvSum[C_CLS];
__device__ float g_rowExp[AROWS];
__device__ float g_rowPos[AROWS];

// ----------------------------- ptx helpers ----------------------------------
__device__ __forceinline__ uint32_t smem_u32(const void* p) {
    uint32_t a;
    asm("{ .reg .u64 t; cvta.to.shared.u64 t, %1; cvt.u32.u64 %0, t; }"
        : "=r"(a) : "l"(p));
    return a;
}

#define CP_ASYNC16(dst, src) \
    asm volatile("cp.async.cg.shared.global [%0], [%1], 16;" :: "r"(dst), "l"(src))
#define CP_ASYNC4(dst, src) \
    asm volatile("cp.async.ca.shared.global [%0], [%1], 4;" :: "r"(dst), "l"(src))
#define CP_COMMIT() asm volatile("cp.async.commit_group;" ::: "memory")
#define CP_WAIT(n)  asm volatile("cp.async.wait_group %0;" :: "n"(n) : "memory")

#define LDSM_X4(r0, r1, r2, r3, addr)                                          \
    asm volatile("ldmatrix.sync.aligned.m8n8.x4.shared.b16 {%0,%1,%2,%3}, [%4];" \
        : "=r"(r0), "=r"(r1), "=r"(r2), "=r"(r3) : "r"(addr))

__device__ __forceinline__ void mma_bf16(float c[4], const uint32_t a[4],
                                         uint32_t b0, uint32_t b1) {
    asm volatile(
        "mma.sync.aligned.m16n8k16.row.col.f32.bf16.bf16.f32 "
        "{%0,%1,%2,%3}, {%4,%5,%6,%7}, {%8,%9}, {%0,%1,%2,%3};"
        : "+f"(c[0]), "+f"(c[1]), "+f"(c[2]), "+f"(c[3])
        : "r"(a[0]), "r"(a[1]), "r"(a[2]), "r"(a[3]), "r"(b0), "r"(b1));
}

__device__ __forceinline__ int pix_label(int n, const int* __restrict__ mg,
                                         const int* __restrict__ ag) {
    int b = n >> 15;
    int j = n & 32767;
    int lab;
    if (j < 16384) {
        int h = j >> 7, w = j & 127;
        lab = mg[(b << 18) + (h << 11) + (w << 2)];
    } else {
        int jj = j - 16384;
        int h = jj >> 7, w = jj & 127;
        lab = ag[(b << 18) + (h << 11) + (w << 2)];
    }
    return lab;
}

// ------------------------------ prep kernels --------------------------------
// init + per-block histogram + label cache
__global__ void k_initcount(const int* __restrict__ mg, const int* __restrict__ ag) {
    __shared__ int hist[C_CLS];
    int tid = threadIdx.x;
    int t = blockIdx.x * SELBLK + tid;
    if (t < AROWS) {
        g_selIdx[t] = -1;
        g_rowExp[t] = 0.f;
        g_rowPos[t] = 0.f;
    }
    if (t < C_CLS) g_cvSum[t] = 0;
    if (tid < C_CLS) hist[tid] = 0;
    __syncthreads();
    int lab = pix_label(t, mg, ag);
    bool valid = (lab != IGNORE_I);
    if (lab == AUX_I) lab = C_CLS - 1;
    g_lab[t] = (unsigned char)(valid ? lab : IGNORE_I);
    if (valid) atomicAdd(&hist[lab], 1);
    __syncthreads();
    if (tid < C_CLS)
        g_blockCounts[blockIdx.x * C_CLS + tid] = hist[tid];
}

// fused scan + stable select; labels from the byte cache
__global__ void k_select() {
    __shared__ int warpHist[16][C_CLS];
    __shared__ int blockBase[C_CLS];
    int tid = threadIdx.x, wid = tid >> 5, lane = tid & 31;

    // per-class base = sum of blockCounts of preceding blocks (warp per class)
    for (int c = wid; c < C_CLS; c += 16) {
        int sum = 0;
        for (int b = lane; b < blockIdx.x; b += 32)
            sum += g_blockCounts[b * C_CLS + c];
        #pragma unroll
        for (int off = 16; off; off >>= 1)
            sum += __shfl_xor_sync(0xffffffffu, sum, off);
        if (lane == 0) {
            blockBase[c] = sum;
            if (blockIdx.x == NBLK - 1)
                g_counts[c] = sum + g_blockCounts[(NBLK - 1) * C_CLS + c];
        }
    }
    for (int i = tid; i < 16 * C_CLS; i += SELBLK) ((int*)warpHist)[i] = 0;
    __syncthreads();

    int n = blockIdx.x * SELBLK + tid;
    int lab = g_lab[n];
    bool valid = (lab != IGNORE_I);
    int key = lab;
    unsigned mask = __match_any_sync(0xffffffffu, key);
    int rank = __popc(mask & ((1u << lane) - 1u));
    if (valid && rank == 0) warpHist[wid][lab] = __popc(mask);
    __syncthreads();
    if (valid) {
        int base = blockBase[lab];
        for (int w2 = 0; w2 < wid; w2++) base += warpHist[w2][lab];
        int slot = base + rank;
        if (slot < MEMM) g_selIdx[lab * MEMM + slot] = n;
    }
}

// gather+normalize + momentum bank update; bank row prefetched concurrently
__global__ void k_gatherbank(const float* __restrict__ mp, const float* __restrict__ ap,
                             const float* __restrict__ bank) {
    int wslot = blockIdx.x * 8 + (threadIdx.x >> 5);
    int lane = threadIdx.x & 31;
    if (wslot >= AROWS) return;
    int n = g_selIdx[wslot];
    int c = wslot >> 9;
    __nv_bfloat16* sdst = g_selb + (size_t)wslot * DIM;
    __nv_bfloat16* cdst = g_contrasb + (size_t)wslot * DIM;
    const float* br = bank + (size_t)wslot * DIM;

    // prefetch bank row (coalesced) so it overlaps the scattered gather
    float bro[8];
    #pragma unroll
    for (int k = 0; k < 8; k++) bro[k] = br[lane + k * 32];

    float u[8];
    float ss = 0.f;
    if (n >= 0) {
        int b = n >> 15, j = n & 32767;
        const float* src;
        if (j < 16384) {
            int h = j >> 7, w = j & 127;
            src = mp + ((size_t)b << 22) + (h << 7) + w;
        } else {
            int jj = j - 16384;
            int h = jj >> 7, w = jj & 127;
            src = ap + ((size_t)b << 22) + (h << 7) + w;
        }
        float v[8];
        float vs = 0.f;
        #pragma unroll
        for (int k = 0; k < 8; k++) {
            v[k] = src[(size_t)(lane + k * 32) << 14];
            vs += v[k] * v[k];
        }
        #pragma unroll
        for (int off = 16; off; off >>= 1) vs += __shfl_xor_sync(0xffffffffu, vs, off);
        float inv = 1.f / fmaxf(sqrtf(vs), 1e-12f);
        #pragma unroll
        for (int k = 0; k < 8; k++) {
            float s = v[k] * inv;
            sdst[lane + k * 32] = __float2bfloat16(s);
            float uu = 0.999f * bro[k] + 0.001f * s;
            u[k] = uu;
            ss += uu * uu;
        }
        #pragma unroll
        for (int off = 16; off; off >>= 1) ss += __shfl_xor_sync(0xffffffffu, ss, off);
        float inv2 = 1.f / fmaxf(sqrtf(ss), 1e-12f);
        #pragma unroll
        for (int k = 0; k < 8; k++)
            cdst[lane + k * 32] = __float2bfloat16(u[k] * inv2);
    } else {
        #pragma unroll
        for (int k = 0; k < 8; k++) {
            sdst[lane + k * 32] = __float2bfloat16(0.f);
            u[k] = bro[k];
            ss += u[k] * u[k];
            cdst[lane + k * 32] = __float2bfloat16(u[k]);
        }
        #pragma unroll
        for (int off = 16; off; off >>= 1) ss += __shfl_xor_sync(0xffffffffu, ss, off);
    }
    if (lane == 0) {
        float cv = (ss > 0.f) ? 1.f : 0.f;
        g_cvalid[wslot] = cv;
        if (cv > 0.f) atomicAdd(&g_cvSum[c], 1);
    }
}

// -------------- persistent bf16 GEMM (round-7 verbatim) ----------------------
// 148 CTAs, 256 threads (8 warps 4x2, warp tile 64x64, frags 4x8 m16n8k16).
__global__ void __launch_bounds__(256, 1) k_gemm_p() {
    extern __shared__ char sm[];
    const uint32_t aBase = smem_u32(sm);
    const uint32_t bBase = aBase + SMO_B;
    const uint32_t cvBase = aBase + SMO_CV;
    float* cvs = (float*)(sm + SMO_CV);

    const int tid = threadIdx.x, lane = tid & 31, wid = tid >> 5;
    const int tig = lane & 3, grp = lane >> 2;
    const int wr = wid >> 1, wc = wid & 1;

    const int aRow = wr * 64 + (lane & 15);
    const int aK   = (lane >> 4) * 8;
    const int bg   = lane >> 3;
    const int bRow = wc * 64 + ((bg >> 1) << 3) + (lane & 7);
    const int bK   = (bg & 1) * 8;

    int t0 = (int)(((long long)blockIdx.x * NTILE) / GRID_P);
    int t1 = (int)(((long long)(blockIdx.x + 1) * NTILE) / GRID_P);

    float c[4][8][4];
    float eAcc[4][2], pAcc[4][2];
    #pragma unroll
    for (int mi = 0; mi < 4; mi++) {
        #pragma unroll
        for (int ni = 0; ni < 8; ni++)
            #pragma unroll
            for (int q = 0; q < 4; q++) c[mi][ni][q] = 0.f;
        eAcc[mi][0] = eAcc[mi][1] = 0.f;
        pAcc[mi][0] = pAcc[mi][1] = 0.f;
    }

    int t = t0;
    while (t < t1) {
        const int band = t / NCT;
        const int ct0 = t % NCT;
        int bandEnd = (band + 1) * NCT;
        if (bandEnd > t1) bandEnd = t1;
        const int nt = bandEnd - t;
        const int total = nt * 4;
        const __nv_bfloat16* Ag = g_selb + (size_t)band * TM * DIM;

        #pragma unroll
        for (int i = 0; i < 32; i++) {
            int ch = tid + i * 256;
            int r = ch >> 5, seg = ch & 31;
            CP_ASYNC16(aBase + r * PADA_B + seg * 16,
                       (const char*)(Ag + (size_t)r * DIM + seg * 8));
        }
        CP_COMMIT();

        auto issue_stage = [&](int g) {
            const int ti = g >> 2, kq = g & 3;
            const int ct = ct0 + ti;
            const __nv_bfloat16* Bg =
                g_contrasb + ((size_t)ct * TN) * DIM + kq * 64;
            const uint32_t bb = bBase + (g & 3) * B_STG;
            #pragma unroll
            for (int i = 0; i < 4; i++) {
                int ch = tid + i * 256;
                int r = ch >> 3, seg = ch & 7;
                CP_ASYNC16(bb + r * PADB_B + seg * 16,
                           (const char*)(Bg + (size_t)r * DIM + seg * 8));
            }
            if (kq == 0 && tid < TN) {
                CP_ASYNC4(cvBase + (ti & 1) * 512 + tid * 4,
                          (const char*)(g_cvalid + ct * TN + tid));
            }
        };

        issue_stage(0); CP_COMMIT();
        issue_stage(1); CP_COMMIT();
        issue_stage(2); CP_COMMIT();

        for (int s = 0; s < total; s++) {
            if (s < total - 2)      { CP_WAIT(2); }
            else if (s == total - 2){ CP_WAIT(1); }
            else                    { CP_WAIT(0); }
            __syncthreads();

            const uint32_t bb = bBase + (s & 3) * B_STG;
            const int kb = (s & 3) * 64;
            #pragma unroll
            for (int ks = 0; ks < 4; ks++) {
                const int kcA = kb + ks * 16;
                const int kcB = ks * 16;
                uint32_t af[4][4];
                #pragma unroll
                for (int mi = 0; mi < 4; mi++) {
                    uint32_t addr = aBase + (aRow + mi * 16) * PADA_B + (kcA + aK) * 2;
                    LDSM_X4(af[mi][0], af[mi][1], af[mi][2], af[mi][3], addr);
                }
                uint32_t bf[8][2];
                #pragma unroll
                for (int p = 0; p < 4; p++) {
                    uint32_t addr = bb + (bRow + p * 16) * PADB_B + (kcB + bK) * 2;
                    uint32_t r0, r1, r2, r3;
                    LDSM_X4(r0, r1, r2, r3, addr);
                    bf[2 * p][0] = r0; bf[2 * p][1] = r1;
                    bf[2 * p + 1][0] = r2; bf[2 * p + 1][1] = r3;
                }
                #pragma unroll
                for (int mi = 0; mi < 4; mi++)
                    #pragma unroll
                    for (int ni = 0; ni < 8; ni++)
                        mma_bf16(c[mi][ni], af[mi], bf[ni][0], bf[ni][1]);
            }

            if ((s & 3) == 3) {
                const int ti = s >> 2;
                const int ct = ct0 + ti;
                const float posf = ((band >> 1) == (ct >> 2)) ? 1.f : 0.f;
                const float* cv = cvs + (ti & 1) * 128;
                float cvr[8][2];
                #pragma unroll
                for (int ni = 0; ni < 8; ni++) {
                    cvr[ni][0] = cv[wc * 64 + ni * 8 + 2 * tig];
                    cvr[ni][1] = cv[wc * 64 + ni * 8 + 2 * tig + 1];
                }
                #pragma unroll
                for (int mi = 0; mi < 4; mi++)
                    #pragma unroll
                    for (int h = 0; h < 2; h++) {
                        float e = 0.f, p = 0.f;
                        #pragma unroll
                        for (int ni = 0; ni < 8; ni++)
                            #pragma unroll
                            for (int j = 0; j < 2; j++) {
                                float sc = c[mi][ni][h * 2 + j] * 10.0f;
                                e += cvr[ni][j] * __expf(sc);
                                p += cvr[ni][j] * sc;
                                c[mi][ni][h * 2 + j] = 0.f;
                            }
                        eAcc[mi][h] += e;
                        pAcc[mi][h] += posf * p;
                    }
            }

            if (s + 3 < total) {
                issue_stage(s + 3);
                CP_COMMIT();
            }
        }

        #pragma unroll
        for (int mi = 0; mi < 4; mi++)
            #pragma unroll
            for (int h = 0; h < 2; h++) {
                float e = eAcc[mi][h], p = pAcc[mi][h];
                e += __shfl_xor_sync(0xffffffffu, e, 1);
                e += __shfl_xor_sync(0xffffffffu, e, 2);
                p += __shfl_xor_sync(0xffffffffu, p, 1);
                p += __shfl_xor_sync(0xffffffffu, p, 2);
                if (tig == 0) {
                    int r = band * TM + wr * 64 + mi * 16 + h * 8 + grp;
                    atomicAdd(&g_rowExp[r], e);
                    atomicAdd(&g_rowPos[r], p);
                }
                eAcc[mi][h] = 0.f;
                pAcc[mi][h] = 0.f;
            }
        __syncthreads();
        t = bandEnd;
    }
}

// ------------------------------- loss ----------------------------------------
__global__ void k_loss(float* __restrict__ out) {
    __shared__ double sred[256];
    __shared__ int cred[256];
    int tid = threadIdx.x;
    double local = 0.0;
    int cnt = 0;
    for (int s = tid; s < AROWS; s += 256) {
        int c = s >> 9, m = s & 511;
        int pc = g_cvSum[c];
        if (m < g_counts[c] && pc > 0) {
            float lse = logf(g_rowExp[s]);
            float mlpp = (g_rowPos[s] - (float)pc * lse) / (float)pc;
            local += (double)mlpp;
            cnt++;
        }
    }
    sred[tid] = local;
    cred[tid] = cnt;
    __syncthreads();
    for (int off = 128; off; off >>= 1) {
        if (tid < off) {
            sred[tid] += sred[tid + off];
            cred[tid] += cred[tid + off];
        }
        __syncthreads();
    }
    if (tid == 0) {
        int n = cred[0] > 0 ? cred[0] : 1;
        out[0] = (float)(-sred[0] / (double)n);
    }
}

// ------------------------------- launcher ------------------------------------
extern "C" void kernel_launch(void* const* d_in, const int* in_sizes, int n_in,
                              void* d_out, int out_size) {
    const float* mp   = (const float*)d_in[0];
    const int*   mg   = (const int*)d_in[1];
    const float* ap   = (const float*)d_in[2];
    const int*   ag   = (const int*)d_in[3];
    const float* bank = (const float*)d_in[4];
    float* out = (float*)d_out;

    cudaFuncSetAttribute(k_gemm_p, cudaFuncAttributeMaxDynamicSharedMemorySize,
                         SMEM_T);

    k_initcount<<<NBLK, SELBLK>>>(mg, ag);        // launch 1
    k_select<<<NBLK, SELBLK>>>();                 // launch 2 (labels cached)
    k_gatherbank<<<AROWS / 8, 256>>>(mp, ap, bank); // launch 3
    k_gemm_p<<<GRID_P, 256, SMEM_T>>>();          // launch 4 -> ncu capture
    k_loss<<<1, 256>>>(out);                      // launch 5
}

// round 14
// speedup vs baseline: 1.1915x; 1.0557x over previous
#include <cuda_runtime.h>
#include <cuda_bf16.h>
#include <math.h>
#include <stdint.h>

// Problem constants
#define NPIX      131072          // 4 * (16384 main + 16384 aux)
#define SELBLK    512
#define NBLK      (NPIX / SELBLK) // 256
#define C_CLS     20
#define MEMM      512
#define AROWS     (C_CLS * MEMM)  // 10240
#define DIM       256
#define IGNORE_I  255
#define AUX_I     254

// Persistent GEMM tiling (round-7 proven config)
#define TM        256             // band rows (A resident)
#define TN        128             // col tile
#define NCT       80              // col tiles per band
#define NTILE     3200            // 40 bands * 80
#define GRID_P    148
#define PADA_B    528             // A smem row stride bytes
#define PADB_B    144             // B smem row stride bytes (64 bf16 + pad)
#define A_BYTES   (256 * PADA_B)  // 135168
#define B_STG     (128 * PADB_B)  // 18432
#define SMO_B     A_BYTES
#define SMO_CV    (A_BYTES + 4 * B_STG)   // 208896
#define SMEM_T    (SMO_CV + 1024)         // 209920

#define EXPC      14.4269504089f  // 10 * log2(e)

// -------- persistent scratch ------------------------------------------------
__device__ int   g_blockCounts[NBLK * C_CLS];
__device__ int   g_counts[C_CLS];
__device__ int   g_selIdx[AROWS];
__device__ unsigned char g_lab[NPIX];
__device__ __nv_bfloat16 g_selb[AROWS * DIM];
__device__ __nv_bfloat16 g_contrasb[AROWS * DIM];
__device__ float g_cvalid[AROWS];
__device__ int   g_cvSum[C_CLS];
__device__ float g_rowExp[AROWS];
__device__ float g_rowPos[AROWS];
__device__ int   g_done;          // last-block counter; reset by k_initcount

// ----------------------------- ptx helpers ----------------------------------
__device__ __forceinline__ uint32_t smem_u32(const void* p) {
    uint32_t a;
    asm("{ .reg .u64 t; cvta.to.shared.u64 t, %1; cvt.u32.u64 %0, t; }"
        : "=r"(a) : "l"(p));
    return a;
}
__device__ __forceinline__ float ex2f(float x) {
    float r;
    asm("ex2.approx.f32 %0, %1;" : "=f"(r) : "f"(x));
    return r;
}

#define CP_ASYNC16(dst, src) \
    asm volatile("cp.async.cg.shared.global [%0], [%1], 16;" :: "r"(dst), "l"(src))
#define CP_ASYNC4(dst, src) \
    asm volatile("cp.async.ca.shared.global [%0], [%1], 4;" :: "r"(dst), "l"(src))
#define CP_COMMIT() asm volatile("cp.async.commit_group;" ::: "memory")
#define CP_WAIT(n)  asm volatile("cp.async.wait_group %0;" :: "n"(n) : "memory")

#define LDSM_X4(r0, r1, r2, r3, addr)                                          \
    asm volatile("ldmatrix.sync.aligned.m8n8.x4.shared.b16 {%0,%1,%2,%3}, [%4];" \
        : "=r"(r0), "=r"(r1), "=r"(r2), "=r"(r3) : "r"(addr))

__device__ __forceinline__ void mma_bf16(float c[4], const uint32_t a[4],
                                         uint32_t b0, uint32_t b1) {
    asm volatile(
        "mma.sync.aligned.m16n8k16.row.col.f32.bf16.bf16.f32 "
        "{%0,%1,%2,%3}, {%4,%5,%6,%7}, {%8,%9}, {%0,%1,%2,%3};"
        : "+f"(c[0]), "+f"(c[1]), "+f"(c[2]), "+f"(c[3])
        : "r"(a[0]), "r"(a[1]), "r"(a[2]), "r"(a[3]), "r"(b0), "r"(b1));
}

__device__ __forceinline__ int pix_label(int n, const int* __restrict__ mg,
                                         const int* __restrict__ ag) {
    int b = n >> 15;
    int j = n & 32767;
    int lab;
    if (j < 16384) {
        int h = j >> 7, w = j & 127;
        lab = mg[(b << 18) + (h << 11) + (w << 2)];
    } else {
        int jj = j - 16384;
        int h = jj >> 7, w = jj & 127;
        lab = ag[(b << 18) + (h << 11) + (w << 2)];
    }
    return lab;
}

// ------------------------------ prep kernels --------------------------------
__global__ void k_initcount(const int* __restrict__ mg, const int* __restrict__ ag) {
    __shared__ int hist[C_CLS];
    int tid = threadIdx.x;
    int t = blockIdx.x * SELBLK + tid;
    if (t < AROWS) {
        g_selIdx[t] = -1;
        g_rowExp[t] = 0.f;
        g_rowPos[t] = 0.f;
    }
    if (t < C_CLS) g_cvSum[t] = 0;
    if (t == 0) g_done = 0;
    if (tid < C_CLS) hist[tid] = 0;
    __syncthreads();
    int lab = pix_label(t, mg, ag);
    bool valid = (lab != IGNORE_I);
    if (lab == AUX_I) lab = C_CLS - 1;
    g_lab[t] = (unsigned char)(valid ? lab : IGNORE_I);
    if (valid) atomicAdd(&hist[lab], 1);
    __syncthreads();
    if (tid < C_CLS)
        g_blockCounts[blockIdx.x * C_CLS + tid] = hist[tid];
}

__global__ void k_select() {
    __shared__ int warpHist[16][C_CLS];
    __shared__ int blockBase[C_CLS];
    int tid = threadIdx.x, wid = tid >> 5, lane = tid & 31;

    for (int c = wid; c < C_CLS; c += 16) {
        int sum = 0;
        for (int b = lane; b < blockIdx.x; b += 32)
            sum += g_blockCounts[b * C_CLS + c];
        #pragma unroll
        for (int off = 16; off; off >>= 1)
            sum += __shfl_xor_sync(0xffffffffu, sum, off);
        if (lane == 0) {
            blockBase[c] = sum;
            if (blockIdx.x == NBLK - 1)
                g_counts[c] = sum + g_blockCounts[(NBLK - 1) * C_CLS + c];
        }
    }
    for (int i = tid; i < 16 * C_CLS; i += SELBLK) ((int*)warpHist)[i] = 0;
    __syncthreads();

    int n = blockIdx.x * SELBLK + tid;
    int lab = g_lab[n];
    bool valid = (lab != IGNORE_I);
    unsigned mask = __match_any_sync(0xffffffffu, lab);
    int rank = __popc(mask & ((1u << lane) - 1u));
    if (valid && rank == 0) warpHist[wid][lab] = __popc(mask);
    __syncthreads();
    if (valid) {
        int base = blockBase[lab];
        for (int w2 = 0; w2 < wid; w2++) base += warpHist[w2][lab];
        int slot = base + rank;
        if (slot < MEMM) g_selIdx[lab * MEMM + slot] = n;
    }
}

__global__ void k_gatherbank(const float* __restrict__ mp, const float* __restrict__ ap,
                             const float* __restrict__ bank) {
    int wslot = blockIdx.x * 8 + (threadIdx.x >> 5);
    int lane = threadIdx.x & 31;
    if (wslot >= AROWS) return;
    int n = g_selIdx[wslot];
    int c = wslot >> 9;
    __nv_bfloat16* sdst = g_selb + (size_t)wslot * DIM;
    __nv_bfloat16* cdst = g_contrasb + (size_t)wslot * DIM;
    const float* br = bank + (size_t)wslot * DIM;

    float bro[8];
    #pragma unroll
    for (int k = 0; k < 8; k++) bro[k] = br[lane + k * 32];

    float u[8];
    float ss = 0.f;
    if (n >= 0) {
        int b = n >> 15, j = n & 32767;
        const float* src;
        if (j < 16384) {
            int h = j >> 7, w = j & 127;
            src = mp + ((size_t)b << 22) + (h << 7) + w;
        } else {
            int jj = j - 16384;
            int h = jj >> 7, w = jj & 127;
            src = ap + ((size_t)b << 22) + (h << 7) + w;
        }
        float v[8];
        float vs = 0.f;
        #pragma unroll
        for (int k = 0; k < 8; k++) {
            v[k] = src[(size_t)(lane + k * 32) << 14];
            vs += v[k] * v[k];
        }
        #pragma unroll
        for (int off = 16; off; off >>= 1) vs += __shfl_xor_sync(0xffffffffu, vs, off);
        float inv = 1.f / fmaxf(sqrtf(vs), 1e-12f);
        #pragma unroll
        for (int k = 0; k < 8; k++) {
            float s = v[k] * inv;
            sdst[lane + k * 32] = __float2bfloat16(s);
            float uu = 0.999f * bro[k] + 0.001f * s;
            u[k] = uu;
            ss += uu * uu;
        }
        #pragma unroll
        for (int off = 16; off; off >>= 1) ss += __shfl_xor_sync(0xffffffffu, ss, off);
        float inv2 = 1.f / fmaxf(sqrtf(ss), 1e-12f);
        #pragma unroll
        for (int k = 0; k < 8; k++)
            cdst[lane + k * 32] = __float2bfloat16(u[k] * inv2);
    } else {
        #pragma unroll
        for (int k = 0; k < 8; k++) {
            sdst[lane + k * 32] = __float2bfloat16(0.f);
            u[k] = bro[k];
            ss += u[k] * u[k];
            cdst[lane + k * 32] = __float2bfloat16(u[k]);
        }
        #pragma unroll
        for (int off = 16; off; off >>= 1) ss += __shfl_xor_sync(0xffffffffu, ss, off);
    }
    if (lane == 0) {
        float cv = (ss > 0.f) ? 1.f : 0.f;
        g_cvalid[wslot] = cv;
        if (cv > 0.f) atomicAdd(&g_cvSum[c], 1);
    }
}

// -------------- persistent bf16 GEMM + fused loss tail -----------------------
__global__ void __launch_bounds__(256, 1) k_gemm_p(float* __restrict__ out) {
    extern __shared__ char sm[];
    const uint32_t aBase = smem_u32(sm);
    const uint32_t bBase = aBase + SMO_B;
    const uint32_t cvBase = aBase + SMO_CV;
    float* cvs = (float*)(sm + SMO_CV);

    const int tid = threadIdx.x, lane = tid & 31, wid = tid >> 5;
    const int tig = lane & 3, grp = lane >> 2;
    const int wr = wid >> 1, wc = wid & 1;

    const int aRow = wr * 64 + (lane & 15);
    const int aK   = (lane >> 4) * 8;
    const int bg   = lane >> 3;
    const int bRow = wc * 64 + ((bg >> 1) << 3) + (lane & 7);
    const int bK   = (bg & 1) * 8;

    int t0 = (int)(((long long)blockIdx.x * NTILE) / GRID_P);
    int t1 = (int)(((long long)(blockIdx.x + 1) * NTILE) / GRID_P);

    float c[4][8][4];
    float eAcc[4][2], pAcc[4][2];
    #pragma unroll
    for (int mi = 0; mi < 4; mi++) {
        #pragma unroll
        for (int ni = 0; ni < 8; ni++)
            #pragma unroll
            for (int q = 0; q < 4; q++) c[mi][ni][q] = 0.f;
        eAcc[mi][0] = eAcc[mi][1] = 0.f;
        pAcc[mi][0] = pAcc[mi][1] = 0.f;
    }

    int t = t0;
    while (t < t1) {
        const int band = t / NCT;
        const int ct0 = t % NCT;
        int bandEnd = (band + 1) * NCT;
        if (bandEnd > t1) bandEnd = t1;
        const int nt = bandEnd - t;
        const int total = nt * 4;
        const __nv_bfloat16* Ag = g_selb + (size_t)band * TM * DIM;

        #pragma unroll
        for (int i = 0; i < 32; i++) {
            int ch = tid + i * 256;
            int r = ch >> 5, seg = ch & 31;
            CP_ASYNC16(aBase + r * PADA_B + seg * 16,
                       (const char*)(Ag + (size_t)r * DIM + seg * 8));
        }
        CP_COMMIT();

        auto issue_stage = [&](int g) {
            const int ti = g >> 2, kq = g & 3;
            const int ct = ct0 + ti;
            const __nv_bfloat16* Bg =
                g_contrasb + ((size_t)ct * TN) * DIM + kq * 64;
            const uint32_t bb = bBase + (g & 3) * B_STG;
            #pragma unroll
            for (int i = 0; i < 4; i++) {
                int ch = tid + i * 256;
                int r = ch >> 3, seg = ch & 7;
                CP_ASYNC16(bb + r * PADB_B + seg * 16,
                           (const char*)(Bg + (size_t)r * DIM + seg * 8));
            }
            if (kq == 0 && tid < TN) {
                CP_ASYNC4(cvBase + (ti & 1) * 512 + tid * 4,
                          (const char*)(g_cvalid + ct * TN + tid));
            }
        };

        issue_stage(0); CP_COMMIT();
        issue_stage(1); CP_COMMIT();
        issue_stage(2); CP_COMMIT();

        for (int s = 0; s < total; s++) {
            if (s < total - 2)      { CP_WAIT(2); }
            else if (s == total - 2){ CP_WAIT(1); }
            else                    { CP_WAIT(0); }
            __syncthreads();

            const uint32_t bb = bBase + (s & 3) * B_STG;
            const int kb = (s & 3) * 64;
            #pragma unroll
            for (int ks = 0; ks < 4; ks++) {
                const int kcA = kb + ks * 16;
                const int kcB = ks * 16;
                uint32_t af[4][4];
                #pragma unroll
                for (int mi = 0; mi < 4; mi++) {
                    uint32_t addr = aBase + (aRow + mi * 16) * PADA_B + (kcA + aK) * 2;
                    LDSM_X4(af[mi][0], af[mi][1], af[mi][2], af[mi][3], addr);
                }
                uint32_t bf[8][2];
                #pragma unroll
                for (int p = 0; p < 4; p++) {
                    uint32_t addr = bb + (bRow + p * 16) * PADB_B + (kcB + bK) * 2;
                    uint32_t r0, r1, r2, r3;
                    LDSM_X4(r0, r1, r2, r3, addr);
                    bf[2 * p][0] = r0; bf[2 * p][1] = r1;
                    bf[2 * p + 1][0] = r2; bf[2 * p + 1][1] = r3;
                }
                #pragma unroll
                for (int mi = 0; mi < 4; mi++)
                    #pragma unroll
                    for (int ni = 0; ni < 8; ni++)
                        mma_bf16(c[mi][ni], af[mi], bf[ni][0], bf[ni][1]);
            }

            if ((s & 3) == 3) {
                const int ti = s >> 2;
                const int ct = ct0 + ti;
                const bool isPos = ((band >> 1) == (ct >> 2));
                const float* cv = cvs + (ti & 1) * 128;
                float cvr[8][2];
                #pragma unroll
                for (int ni = 0; ni < 8; ni++) {
                    cvr[ni][0] = cv[wc * 64 + ni * 8 + 2 * tig];
                    cvr[ni][1] = cv[wc * 64 + ni * 8 + 2 * tig + 1];
                }
                if (isPos) {
                    #pragma unroll
                    for (int mi = 0; mi < 4; mi++)
                        #pragma unroll
                        for (int h = 0; h < 2; h++) {
                            float e = 0.f, p = 0.f;
                            #pragma unroll
                            for (int ni = 0; ni < 8; ni++)
                                #pragma unroll
                                for (int j = 0; j < 2; j++) {
                                    float a = c[mi][ni][h * 2 + j];
                                    e += cvr[ni][j] * ex2f(a * EXPC);
                                    p += cvr[ni][j] * a;
                                    c[mi][ni][h * 2 + j] = 0.f;
                                }
                            eAcc[mi][h] += e;
                            pAcc[mi][h] += p;
                        }
                } else {
                    #pragma unroll
                    for (int mi = 0; mi < 4; mi++)
                        #pragma unroll
                        for (int h = 0; h < 2; h++) {
                            float e = 0.f;
                            #pragma unroll
                            for (int ni = 0; ni < 8; ni++)
                                #pragma unroll
                                for (int j = 0; j < 2; j++) {
                                    float a = c[mi][ni][h * 2 + j];
                                    e += cvr[ni][j] * ex2f(a * EXPC);
                                    c[mi][ni][h * 2 + j] = 0.f;
                                }
                            eAcc[mi][h] += e;
                        }
                }
            }

            if (s + 3 < total) {
                issue_stage(s + 3);
                CP_COMMIT();
            }
        }

        #pragma unroll
        for (int mi = 0; mi < 4; mi++)
            #pragma unroll
            for (int h = 0; h < 2; h++) {
                float e = eAcc[mi][h], p = pAcc[mi][h] * 10.0f;
                e += __shfl_xor_sync(0xffffffffu, e, 1);
                e += __shfl_xor_sync(0xffffffffu, e, 2);
                p += __shfl_xor_sync(0xffffffffu, p, 1);
                p += __shfl_xor_sync(0xffffffffu, p, 2);
                if (tig == 0) {
                    int r = band * TM + wr * 64 + mi * 16 + h * 8 + grp;
                    atomicAdd(&g_rowExp[r], e);
                    atomicAdd(&g_rowPos[r], p);
                }
                eAcc[mi][h] = 0.f;
                pAcc[mi][h] = 0.f;
            }
        __syncthreads();
        t = bandEnd;
    }

    // ---- fused loss: last CTA to arrive computes the final scalar ----
    __threadfence();
    int* flag = (int*)sm;
    if (tid == 0) {
        int prev = atomicAdd(&g_done, 1);
        *flag = (prev == GRID_P - 1) ? 1 : 0;
    }
    __syncthreads();
    if (*flag) {
        double* sred = (double*)(sm + 1024);
        int* cred = (int*)(sm + 1024 + 2048);
        double local = 0.0;
        int cnt = 0;
        for (int s2 = tid; s2 < AROWS; s2 += 256) {
            int cc = s2 >> 9, m = s2 & 511;
            int pc = g_cvSum[cc];
            if (m < g_counts[cc] && pc > 0) {
                float lse = logf(g_rowExp[s2]);
                float mlpp = (g_rowPos[s2] - (float)pc * lse) / (float)pc;
                local += (double)mlpp;
                cnt++;
            }
        }
        sred[tid] = local;
        cred[tid] = cnt;
        __syncthreads();
        for (int off = 128; off; off >>= 1) {
            if (tid < off) {
                sred[tid] += sred[tid + off];
                cred[tid] += cred[tid + off];
            }
            __syncthreads();
        }
        if (tid == 0) {
            int nn = cred[0] > 0 ? cred[0] : 1;
            out[0] = (float)(-sred[0] / (double)nn);
        }
    }
}

// ------------------------------- launcher ------------------------------------
extern "C" void kernel_launch(void* const* d_in, const int* in_sizes, int n_in,
                              void* d_out, int out_size) {
    const float* mp   = (const float*)d_in[0];
    const int*   mg   = (const int*)d_in[1];
    const float* ap   = (const float*)d_in[2];
    const int*   ag   = (const int*)d_in[3];
    const float* bank = (const float*)d_in[4];
    float* out = (float*)d_out;

    cudaFuncSetAttribute(k_gemm_p, cudaFuncAttributeMaxDynamicSharedMemorySize,
                         SMEM_T);

    k_initcount<<<NBLK, SELBLK>>>(mg, ag);          // launch 1
    k_select<<<NBLK, SELBLK>>>();                   // launch 2
    k_gatherbank<<<AROWS / 8, 256>>>(mp, ap, bank); // launch 3
    k_gemm_p<<<GRID_P, 256, SMEM_T>>>(out);         // launch 4 (loss fused)
}